// round 6
// baseline (speedup 1.0000x reference)
#include <cuda_runtime.h>
#include <math.h>
#include <float.h>

#define Tn   512
#define Bn   64
#define En   256
#define Hn   512
#define G4   2048
#define NBLK 128
#define NTHR 256

// Scratch (device globals: the sanctioned alloc-free scratch mechanism)
__device__ float    g_xg[(size_t)Tn * G4 * Bn];  // [t][j][b]  256 MB
__device__ float    g_h[2][Hn * Bn];             // ping-pong, [hidx][b]
__device__ float    g_feat[Hn * Bn];             // [hidx][b]
__device__ unsigned g_count;                     // barrier arrivals (self-resetting)
__device__ unsigned g_gen;                       // barrier generation (free-running)

// ---------------------------------------------------------------------------
// Grid-wide barrier (all NBLK blocks co-resident: 1 block/SM, NBLK <= SM count)
// Release/acquire via gpu-scope fences; backoff spin to keep L2 traffic sane.
// ---------------------------------------------------------------------------
__device__ __forceinline__ void grid_barrier() {
    __syncthreads();
    if (threadIdx.x == 0) {
        volatile unsigned* genp = (volatile unsigned*)&g_gen;
        const unsigned cur = *genp;
        __threadfence();                            // release my step's writes
        if (atomicAdd(&g_count, 1u) == NBLK - 1) {
            g_count = 0u;
            __threadfence();
            *genp = cur + 1u;
        } else {
            while (*genp == cur) { __nanosleep(64); }
            __threadfence();                        // acquire (flushes L1D)
        }
    }
    __syncthreads();
}

// ---------------------------------------------------------------------------
// Kernel 1: fused embedding gather + input projection GEMM
//   xg[t][j][b] = sum_e emb[x[b,t]][e] * W_ih[j][e] + (b_ih[j] + b_hh[j])
// Grid: (16 j-tiles of 128, 512 t), block 256 threads, tile 128x64, BK=32.
// ---------------------------------------------------------------------------
__global__ __launch_bounds__(256)
void embed_gemm_kernel(const int*   __restrict__ x,
                       const float* __restrict__ emb,
                       const float* __restrict__ Wih,
                       const float* __restrict__ bih,
                       const float* __restrict__ bhh) {
    __shared__ float sW[32][132];   // [k][j], pad keeps float4 alignment
    __shared__ float sE[32][68];    // [k][b]
    __shared__ int   sTok[Bn];

    const int tid   = threadIdx.x;
    const int jBase = blockIdx.x * 128;
    const int t     = blockIdx.y;

    if (tid < Bn) sTok[tid] = x[tid * Tn + t];
    __syncthreads();

    const int tb = tid & 15;    // b-group (4 batches)
    const int tj = tid >> 4;    // j-group (8 rows)

    float acc[8][4];
#pragma unroll
    for (int jj = 0; jj < 8; ++jj)
#pragma unroll
        for (int bb = 0; bb < 4; ++bb) acc[jj][bb] = 0.f;

    for (int kc = 0; kc < En; kc += 32) {
#pragma unroll
        for (int i = 0; i < 16; ++i) {                 // 128x32 W chunk
            int idx = tid + i * 256;
            int k = idx & 31, j = idx >> 5;
            sW[k][j] = Wih[(size_t)(jBase + j) * En + kc + k];
        }
#pragma unroll
        for (int i = 0; i < 8; ++i) {                  // 64x32 emb chunk (gathered)
            int idx = tid + i * 256;
            int k = idx & 31, b = idx >> 5;
            sE[k][b] = emb[(size_t)sTok[b] * En + kc + k];
        }
        __syncthreads();

#pragma unroll
        for (int k = 0; k < 32; ++k) {
            const float4 ev = *reinterpret_cast<const float4*>(&sE[k][tb * 4]);
            const float4 wa = *reinterpret_cast<const float4*>(&sW[k][tj * 8]);
            const float4 wb = *reinterpret_cast<const float4*>(&sW[k][tj * 8 + 4]);
            const float e4[4] = {ev.x, ev.y, ev.z, ev.w};
            const float w8[8] = {wa.x, wa.y, wa.z, wa.w, wb.x, wb.y, wb.z, wb.w};
#pragma unroll
            for (int jj = 0; jj < 8; ++jj)
#pragma unroll
                for (int bb = 0; bb < 4; ++bb)
                    acc[jj][bb] += w8[jj] * e4[bb];
        }
        __syncthreads();
    }

    float* xg_t = g_xg + (size_t)t * (G4 * Bn);
#pragma unroll
    for (int jj = 0; jj < 8; ++jj) {
        const int j = jBase + tj * 8 + jj;
        const float bias = bih[j] + bhh[j];
        float4 v = make_float4(acc[jj][0] + bias, acc[jj][1] + bias,
                               acc[jj][2] + bias, acc[jj][3] + bias);
        *reinterpret_cast<float4*>(&xg_t[(size_t)j * Bn + tb * 4]) = v;
    }
}

// ---------------------------------------------------------------------------
// Kernel 2: persistent LSTM recurrence + ragged max-pool.
// Block p owns h indices [4p, 4p+4) i.e. 16 W_hh rows (cached in smem), all
// 64 batches. Threads: 4 hidx x 16 b-groups x 4 k-slices. One grid barrier per
// step; h ping-pongs between two global buffers. All cross-SM h traffic uses
// __ldcg (L2-coherent, L1-bypassed) so correctness never depends on L1 flush.
// Dynamic smem: sH[512*64] + sW[512*16] + sP[64*68] + sXg[16*64]
// ---------------------------------------------------------------------------
#define LSTM_SMEM ((Hn * Bn + Hn * 16 + 64 * 68 + 16 * Bn) * (int)sizeof(float))

__global__ __launch_bounds__(NTHR, 1)
void lstm_kernel(const float* __restrict__ Whh,
                 const int*   __restrict__ length) {
    extern __shared__ float sm[];
    float* sH  = sm;                   // [k][b]        512*64
    float* sW  = sH + Hn * Bn;         // [k][hl*4+g]   512*16
    float* sP  = sW + Hn * 16;         // [(ks,hl,g)][b pad 68]
    float* sXg = sP + 64 * 68;         // [(g,hl)][b]   16*64

    const int tid  = threadIdx.x;
    const int p    = blockIdx.x;
    const int hrow = p * 4;

    const int hl = tid & 3;            // dot-phase: local h index
    const int bg = (tid >> 2) & 15;    //            batch group (4)
    const int ks = tid >> 6;           //            k slice (128 wide)
    const int b0 = bg * 4;
    const int k0 = ks * 128;

    const int he = tid >> 6;           // epilogue: local h index (0..3)
    const int be = tid & 63;           //           batch (0..63)

    // Load this block's 16 W_hh rows, interleaved so hl's 4 gates are a float4.
#pragma unroll
    for (int r = 0; r < 16; ++r) {
        const int g = r & 3, hh = r >> 2;
        const float* src = Whh + (size_t)(g * Hn + hrow + hh) * Hn;
        for (int k = tid; k < Hn; k += NTHR)
            sW[k * 16 + hh * 4 + g] = src[k];
    }
    // Zero this block's rows of h buffer 0 (fresh state every launch/replay).
    for (int i = tid; i < 4 * Bn; i += NTHR)
        g_h[0][hrow * Bn + i] = 0.f;

    float c_state = 0.f;
    float maxv    = -FLT_MAX;
    const int mylen = length[be];

    __threadfence();
    grid_barrier();

    for (int t = 0; t < Tn; ++t) {
        const float* hsrc = g_h[t & 1];
        float*       hdst = g_h[(t + 1) & 1];

        // Phase 1: stage full h[512][64] (L2-coherent loads) and this step's
        // xg slice into smem.
        {
            const float4* s4 = (const float4*)hsrc;
            float4*       d4 = (float4*)sH;
#pragma unroll 8
            for (int i = tid; i < Hn * Bn / 4; i += NTHR) d4[i] = __ldcg(&s4[i]);
        }
        {
            const float* xg_t = g_xg + (size_t)t * (G4 * Bn);
#pragma unroll
            for (int i = tid; i < 16 * Bn; i += NTHR) {
                int b = i & 63, r = i >> 6;
                int g = r >> 2, hh = r & 3;
                sXg[i] = xg_t[(size_t)(g * Hn + hrow + hh) * Bn + b];
            }
        }
        __syncthreads();

        // Phase 2: partial dot products (k slice of 128), 16 accumulators.
        float a[4][4];
#pragma unroll
        for (int g = 0; g < 4; ++g)
#pragma unroll
            for (int bb = 0; bb < 4; ++bb) a[g][bb] = 0.f;
        {
            const float* pH = sH + k0 * Bn + b0;
            const float* pW = sW + k0 * 16 + hl * 4;
#pragma unroll 4
            for (int k = 0; k < 128; ++k) {
                const float4 hv = *reinterpret_cast<const float4*>(pH + k * Bn);
                const float4 wv = *reinterpret_cast<const float4*>(pW + k * 16);
                const float h4[4] = {hv.x, hv.y, hv.z, hv.w};
                const float w4[4] = {wv.x, wv.y, wv.z, wv.w};
#pragma unroll
                for (int g = 0; g < 4; ++g)
#pragma unroll
                    for (int bb = 0; bb < 4; ++bb)
                        a[g][bb] += w4[g] * h4[bb];
            }
        }
        {
            const int rbase = (ks * 4 + hl) * 4;
#pragma unroll
            for (int g = 0; g < 4; ++g)
                *reinterpret_cast<float4*>(&sP[(rbase + g) * 68 + b0]) =
                    make_float4(a[g][0], a[g][1], a[g][2], a[g][3]);
        }
        __syncthreads();

        // Phase 3: epilogue — thread (he, be) owns one (h-index, batch) cell.
        {
            float gi = sXg[(0 * 4 + he) * 64 + be];
            float gf = sXg[(1 * 4 + he) * 64 + be];
            float gg = sXg[(2 * 4 + he) * 64 + be];
            float go = sXg[(3 * 4 + he) * 64 + be];
#pragma unroll
            for (int q = 0; q < 4; ++q) {
                const int rb = (q * 4 + he) * 4;
                gi += sP[(rb + 0) * 68 + be];
                gf += sP[(rb + 1) * 68 + be];
                gg += sP[(rb + 2) * 68 + be];
                go += sP[(rb + 3) * 68 + be];
            }
            const float is = 1.f / (1.f + __expf(-gi));
            const float fs = 1.f / (1.f + __expf(-gf));
            const float gt = tanhf(gg);
            const float os = 1.f / (1.f + __expf(-go));
            c_state = fs * c_state + is * gt;
            const float h = os * tanhf(c_state);
            hdst[(hrow + he) * Bn + be] = h;
            if (t < mylen) maxv = fmaxf(maxv, h);
        }
        grid_barrier();   // includes release fence for hdst writes
    }

    g_feat[(hrow + he) * Bn + be] = maxv;
}

// ---------------------------------------------------------------------------
// Kernel 3: classifier  out[b][c] = sum_h feat[h][b] * W_cls[c][h] + b_cls[c]
// ---------------------------------------------------------------------------
__global__ void cls_kernel(const float* __restrict__ Wcls,
                           const float* __restrict__ bcls,
                           float* __restrict__ out) {
    const int tid = threadIdx.x;   // 128 threads
    const int b = tid >> 1, c = tid & 1;
    float s = bcls[c];
#pragma unroll 8
    for (int h = 0; h < Hn; ++h)
        s += g_feat[h * Bn + b] * Wcls[c * Hn + h];
    out[b * 2 + c] = s;
}

// ---------------------------------------------------------------------------
extern "C" void kernel_launch(void* const* d_in, const int* in_sizes, int n_in,
                              void* d_out, int out_size) {
    const int*   x      = (const int*)  d_in[0];  // [64,512] int32
    const int*   length = (const int*)  d_in[1];  // [64,1]   int32
    const float* emb    = (const float*)d_in[2];  // [32000,256]
    const float* Wih    = (const float*)d_in[3];  // [2048,256]
    const float* Whh    = (const float*)d_in[4];  // [2048,512]
    const float* bih    = (const float*)d_in[5];  // [2048]
    const float* bhh    = (const float*)d_in[6];  // [2048]
    const float* Wcls   = (const float*)d_in[7];  // [2,512]
    const float* bcls   = (const float*)d_in[8];  // [2]
    float* out = (float*)d_out;                   // [64,2]

    cudaFuncSetAttribute(lstm_kernel,
                         cudaFuncAttributeMaxDynamicSharedMemorySize, LSTM_SMEM);

    embed_gemm_kernel<<<dim3(16, Tn), 256>>>(x, emb, Wih, bih, bhh);
    lstm_kernel<<<NBLK, NTHR, LSTM_SMEM>>>(Whh, length);
    cls_kernel<<<1, 128>>>(Wcls, bcls, out);
    (void)in_sizes; (void)n_in; (void)out_size;
}